// round 15
// baseline (speedup 1.0000x reference)
#include <cuda_runtime.h>
#include <cuda_fp16.h>
#include <math.h>
#include <stdint.h>

// ---- problem constants ----
#define B_   16
#define L_   128
#define O_   128
#define N_   256
#define S_   64
#define U_   32
#define DEL  64
#define HID  512
#define KC   4
#define CDIM 288           // N_ + U_
#define TOK  2048          // B_ * L_
#define KDIM 288
#define NBM  8192          // N_*U_  (Bm cols)
#define NCM  16384         // N_*S_  (Cm cols)
#define WROWS (NBM + NCM)  // 24576 fp16 Wg rows (starting at DEL)
#define NYT  128           // y n-tiles (NCM/128)

// ---- scratch (device globals) ----
__device__ __align__(16) float  g_p[TOK * N_];
__device__ __align__(16) __half g_old[TOK * CDIM];
__device__ __align__(16) __half g_wgt[(size_t)WROWS * KDIM];  // fp16 Wg[64:]
__device__ __align__(16) __half g_wc[N_ * KDIM];
__device__ float g_bc[N_];
__device__ __align__(16) float g_dpre[TOK * N_];
__device__ float g_buraw[TOK * N_];
__device__ float g_z[TOK * N_];
__device__ __align__(16) float g_ys[(size_t)NYT * TOK * S_];  // per-ntile y slices
__device__ float g_part[TOK];

__device__ __forceinline__ float siluf(float v) { return v / (1.0f + expf(-v)); }

__device__ __forceinline__ void mma16(float* c, const uint32_t* a, const uint32_t* b) {
    asm volatile("mma.sync.aligned.m16n8k16.row.col.f32.f16.f16.f32 "
        "{%0,%1,%2,%3}, {%4,%5,%6,%7}, {%8,%9}, {%0,%1,%2,%3};"
        : "+f"(c[0]), "+f"(c[1]), "+f"(c[2]), "+f"(c[3])
        : "r"(a[0]), "r"(a[1]), "r"(a[2]), "r"(a[3]), "r"(b[0]), "r"(b[1]));
}
__device__ __forceinline__ void cp16(uint32_t d, const void* s) {
    asm volatile("cp.async.cg.shared.global [%0], [%1], 16;"
                 :: "r"(d), "l"(__cvta_generic_to_global(s)));
}
#define CPCOMMIT() asm volatile("cp.async.commit_group;" ::: "memory")
#define CPWAIT1()  asm volatile("cp.async.wait_group 1;" ::: "memory")
#define CPWAIT0()  asm volatile("cp.async.wait_group 0;" ::: "memory")

// ------------------------------------------------------------------
// 3-stage fp16 GEMM tile: BM=128, BN=128, BK=32 halves, K=288 (9 iters).
// SMEM: stage s at s*4096 words: A (128 rows x 16 words) then B.
// Swizzle: word(r, w) = r*16 + ((w>>2) ^ ((r>>1)&3))*4 + (w&3)
// Fragment map (8 warps, warp tile 64x32):
//  rows r0 = m0 + (wid>>2)*64 + mt*16 + (lane>>2), r0+8   (mt 0..3)
//  cols c  = (wid&3)*32 + nt*8 + (lane&3)*2, c+1           (nt 0..3)
// ------------------------------------------------------------------
#define STGW 4096   // words per stage (16 KB)

__device__ __forceinline__ void pipe_issue(uint32_t sbase, int stage,
                                           const __half* __restrict__ Aptr,
                                           const __half* __restrict__ Bptr,
                                           int k0, int tid) {
    uint32_t aB = sbase + (uint32_t)stage * STGW * 4u;
    uint32_t bB = aB + 2048u * 4u;
    #pragma unroll
    for (int p = 0; p < 2; p++) {
        int idx = tid + p * 256;
        int r = idx >> 2, c0 = idx & 3;
        uint32_t off = (uint32_t)(r * 16 + ((c0 ^ ((r >> 1) & 3)) << 2)) * 4u;
        cp16(aB + off, Aptr + (size_t)r * KDIM + k0 + c0 * 8);
        cp16(bB + off, Bptr + (size_t)r * KDIM + k0 + c0 * 8);
    }
}

__device__ __forceinline__ void gemm_pipe(uint32_t* sm, uint32_t sbase,
                                          const __half* __restrict__ Aptr,
                                          const __half* __restrict__ Bptr,
                                          int tid, float acc[4][4][4]) {
    int lane = tid & 31, wid = tid >> 5;
    int wm = wid >> 2, wn = wid & 3;
    int group = lane >> 2, tid4 = lane & 3;
    int mBase = wm * 64, nBase = wn * 32;
    int sw = (group >> 1) & 3;

    #pragma unroll
    for (int i = 0; i < 4; i++)
        #pragma unroll
        for (int j = 0; j < 4; j++)
            #pragma unroll
            for (int q = 0; q < 4; q++) acc[i][j][q] = 0.0f;

    pipe_issue(sbase, 0, Aptr, Bptr, 0, tid);
    CPCOMMIT();
    pipe_issue(sbase, 1, Aptr, Bptr, 32, tid);
    CPCOMMIT();

    #pragma unroll 1
    for (int it = 0; it < 9; it++) {
        if (it < 8) { CPWAIT1(); } else { CPWAIT0(); }
        __syncthreads();
        if (it + 2 < 9) {
            pipe_issue(sbase, (it + 2) % 3, Aptr, Bptr, (it + 2) * 32, tid);
            CPCOMMIT();
        }

        const uint32_t* sA = sm + (it % 3) * STGW;
        const uint32_t* sB = sA + 2048;

        #pragma unroll
        for (int ks = 0; ks < 2; ks++) {
            int wlo = (((2 * ks)     ^ sw) << 2) + tid4;
            int whi = (((2 * ks + 1) ^ sw) << 2) + tid4;
            uint32_t af[4][4], bf[4][2];
            #pragma unroll
            for (int mt = 0; mt < 4; mt++) {
                int m = mBase + mt * 16 + group;
                af[mt][0] = sA[m * 16 + wlo];
                af[mt][1] = sA[(m + 8) * 16 + wlo];
                af[mt][2] = sA[m * 16 + whi];
                af[mt][3] = sA[(m + 8) * 16 + whi];
            }
            #pragma unroll
            for (int nt = 0; nt < 4; nt++) {
                int n = nBase + nt * 8 + group;
                bf[nt][0] = sB[n * 16 + wlo];
                bf[nt][1] = sB[n * 16 + whi];
            }
            #pragma unroll
            for (int mt = 0; mt < 4; mt++)
                #pragma unroll
                for (int nt = 0; nt < 4; nt++)
                    mma16(acc[mt][nt], af[mt], bf[nt]);
        }
    }
}

// ------------------------------------------------------------------
// K1: proj_x
// ------------------------------------------------------------------
__global__ void __launch_bounds__(256) k_proj(const float* __restrict__ x,
                                              const float* __restrict__ W0,
                                              const float* __restrict__ b0,
                                              const float* __restrict__ W1,
                                              const float* __restrict__ b1) {
    __shared__ float xs[8][64];
    __shared__ float hs[8][512];
    int b  = blockIdx.x >> 4;
    int t0 = (blockIdx.x & 15) * 8;
    int tid = threadIdx.x;

    for (int i = tid; i < 8 * 64; i += 256) {
        int tt = i >> 6, k = i & 63;
        xs[tt][k] = x[(b * (O_ + L_) + t0 + tt) * S_ + k];
    }
    __syncthreads();

    #pragma unroll
    for (int jj = 0; jj < 2; jj++) {
        int j = tid + jj * 256;
        float acc[8];
        float bj = b0[j];
        #pragma unroll
        for (int tt = 0; tt < 8; tt++) acc[tt] = bj;
        for (int k = 0; k < 64; k++) {
            float w = W0[j * 64 + k];
            #pragma unroll
            for (int tt = 0; tt < 8; tt++) acc[tt] += w * xs[tt][k];
        }
        #pragma unroll
        for (int tt = 0; tt < 8; tt++) hs[tt][j] = fmaxf(acc[tt], 0.0f);
    }
    __syncthreads();

    int n = tid;
    float acc2[8];
    float bn = b1[n];
    #pragma unroll
    for (int tt = 0; tt < 8; tt++) acc2[tt] = bn;
    for (int j = 0; j < 512; j++) {
        float w = W1[n * 512 + j];
        #pragma unroll
        for (int tt = 0; tt < 8; tt++) acc2[tt] += w * hs[tt][j];
    }
    #pragma unroll
    for (int tt = 0; tt < 8; tt++) g_p[(b * L_ + t0 + tt) * N_ + n] = acc2[tt];
}

// ------------------------------------------------------------------
// K2: silu -> depthwise conv -> silu, output fp16.
// ------------------------------------------------------------------
__global__ void k_conv(const float* __restrict__ u,
                       const float* __restrict__ cw,
                       const float* __restrict__ cb) {
    int tok = blockIdx.x;
    int b = tok >> 7, l = tok & 127;
    int c = threadIdx.x;   // 0..287
    float acc = cb[c];
    #pragma unroll
    for (int k = 0; k < KC; k++) {
        int i = l - 1 + k;
        if (i >= 0 && i <= 126) {
            float v = (c < 256) ? g_p[((b << 7) + i) * N_ + c]
                                : u[(b * 256 + i) * U_ + (c - 256)];
            acc += cw[c * 4 + k] * siluf(v);
        }
    }
    g_old[tok * CDIM + c] = __float2half_rn(siluf(acc));
}

// ------------------------------------------------------------------
// K3a: fp16-convert Wg rows DEL.. into g_wgt.
// ------------------------------------------------------------------
struct h4pack { __half2 a, b; };
__global__ void k_wround(const float* __restrict__ Wg) {
    const float4* src = reinterpret_cast<const float4*>(Wg + (size_t)DEL * KDIM);
    h4pack* dst = reinterpret_cast<h4pack*>(g_wgt);
    int total = (WROWS * KDIM) / 4;
    for (int i = blockIdx.x * blockDim.x + threadIdx.x; i < total;
         i += gridDim.x * blockDim.x) {
        float4 v = src[i];
        h4pack o;
        o.a = __floats2half2_rn(v.x, v.y);
        o.b = __floats2half2_rn(v.z, v.w);
        dst[i] = o;
    }
}

// ------------------------------------------------------------------
// K3b: Wc = Wdt @ Wg[0:64] (fp16), bc.
// ------------------------------------------------------------------
__global__ void k_wcomb(const float* __restrict__ Wg, const float* __restrict__ bg,
                        const float* __restrict__ Wdt, const float* __restrict__ bdt) {
    __shared__ float sw[64];
    int n = blockIdx.x;       // 0..255
    int tid = threadIdx.x;    // 0..287
    if (tid < 64) sw[tid] = Wdt[n * 64 + tid];
    __syncthreads();
    float acc = 0.0f;
    #pragma unroll 8
    for (int d = 0; d < 64; d++) acc += sw[d] * Wg[d * KDIM + tid];
    g_wc[n * KDIM + tid] = __float2half_rn(acc);
    if (tid == 0) {
        float s = bdt[n];
        for (int d = 0; d < 64; d++) s += sw[d] * bg[d];
        g_bc[n] = s;
    }
}

// ------------------------------------------------------------------
// K4: delta GEMM: g_dpre = old @ Wc^T  (M=2048, N=256)
// ------------------------------------------------------------------
__global__ void __launch_bounds__(256, 2) k_gemm_delta() {
    __shared__ uint32_t sm[3 * STGW];
    uint32_t sbase = (uint32_t)__cvta_generic_to_shared(sm);
    int m0 = blockIdx.y * 128;
    int n0 = blockIdx.x * 128;
    int tid = threadIdx.x;
    int lane = tid & 31, wid = tid >> 5;
    int wm = wid >> 2, wn = wid & 3;
    int group = lane >> 2, tid4 = lane & 3;

    float acc[4][4][4];
    gemm_pipe(sm, sbase, &g_old[(size_t)m0 * KDIM], &g_wc[(size_t)n0 * KDIM], tid, acc);

    #pragma unroll
    for (int mt = 0; mt < 4; mt++) {
        int r0 = m0 + wm * 64 + mt * 16 + group;
        #pragma unroll
        for (int nt = 0; nt < 4; nt++) {
            int c = n0 + wn * 32 + nt * 8 + tid4 * 2;
            *reinterpret_cast<float2*>(&g_dpre[r0 * N_ + c]) =
                make_float2(acc[mt][nt][0], acc[mt][nt][1]);
            *reinterpret_cast<float2*>(&g_dpre[(r0 + 8) * N_ + c]) =
                make_float2(acc[mt][nt][2], acc[mt][nt][3]);
        }
    }
}

// ------------------------------------------------------------------
// K5: Bm GEMM + fused Bu epilogue. BN=128: warp wn owns one n (32 u-cols).
// ------------------------------------------------------------------
__global__ void __launch_bounds__(256, 2) k_gemm_bu(const float* __restrict__ bg,
                                                    const float* __restrict__ u) {
    __shared__ uint32_t sm[3 * STGW];
    uint32_t sbase = (uint32_t)__cvta_generic_to_shared(sm);
    int m0 = blockIdx.y * 128;
    int n0 = blockIdx.x * 128;     // local Bm col
    int tid = threadIdx.x;
    int lane = tid & 31, wid = tid >> 5;
    int wm = wid >> 2, wn = wid & 3;
    int group = lane >> 2, tid4 = lane & 3;

    float acc[4][4][4];
    gemm_pipe(sm, sbase, &g_old[(size_t)m0 * KDIM], &g_wgt[(size_t)n0 * KDIM], tid, acc);

    int nb = blockIdx.x * 4 + wn;
    const float* bgp = &bg[DEL + n0 + wn * 32];

    #pragma unroll
    for (int mt = 0; mt < 4; mt++) {
        int r0 = m0 + wm * 64 + mt * 16 + group;
        int r1 = r0 + 8;
        const float* u0p = &u[((r0 >> 7) * 256 + 127 + (r0 & 127)) * U_];
        const float* u1p = &u[((r1 >> 7) * 256 + 127 + (r1 & 127)) * U_];
        float s0 = 0.0f, s1 = 0.0f;
        #pragma unroll
        for (int nt = 0; nt < 4; nt++) {
            int uu = nt * 8 + tid4 * 2;
            float bg0 = bgp[uu], bg1 = bgp[uu + 1];
            s0 += (acc[mt][nt][0] + bg0) * u0p[uu] + (acc[mt][nt][1] + bg1) * u0p[uu + 1];
            s1 += (acc[mt][nt][2] + bg0) * u1p[uu] + (acc[mt][nt][3] + bg1) * u1p[uu + 1];
        }
        s0 += __shfl_xor_sync(0xffffffffu, s0, 1);
        s0 += __shfl_xor_sync(0xffffffffu, s0, 2);
        s1 += __shfl_xor_sync(0xffffffffu, s1, 1);
        s1 += __shfl_xor_sync(0xffffffffu, s1, 2);
        if (tid4 == 0) {
            g_buraw[r0 * N_ + nb] = s0;
            g_buraw[r1 * N_ + nb] = s1;
        }
    }
}

// ------------------------------------------------------------------
// K6: fused delta-transform + sequential scan (128 blocks x 32 threads).
// ------------------------------------------------------------------
__global__ void __launch_bounds__(32) k_scan(const float* __restrict__ A) {
    int b = blockIdx.x >> 3;
    int n = ((blockIdx.x & 7) << 5) + threadIdx.x;
    float a = A[n];
    float an = (a > 0.0f) ? -a : -expm1f(a);
    float inv_an = 1.0f / an;
    float bcn = g_bc[n];
    float z = g_p[((b << 7) + 127) * N_ + n];
    for (int t0 = 0; t0 < L_; t0 += 8) {
        float dp[8], bu[8], da[8], cb[8];
        #pragma unroll
        for (int q = 0; q < 8; q++) {
            int idx = ((b << 7) + t0 + q) * N_ + n;
            dp[q] = g_dpre[idx];
            bu[q] = g_buraw[idx];
        }
        #pragma unroll
        for (int q = 0; q < 8; q++) {
            float acc = dp[q] + bcn;
            float sp = fmaxf(acc, 0.0f) + log1pf(expf(-fabsf(acc)));
            da[q] = expf(sp * an);
            cb[q] = (da[q] - 1.0f) * inv_an * bu[q];
        }
        #pragma unroll
        for (int q = 0; q < 8; q++) {
            z = z * da[q] + cb[q];
            g_z[((b << 7) + t0 + q) * N_ + n] = z;
        }
    }
}

// ------------------------------------------------------------------
// K7: Cm GEMM + fused y epilogue. Two-phase smem reduction into
// padded ys[128][65], plain stores to per-ntile slice (no atomics).
// ------------------------------------------------------------------
#define YSW 65
#define GSMEM_Y (3 * STGW * 4 + 128 * YSW * 4)

__global__ void __launch_bounds__(256, 2) k_gemm_y(const float* __restrict__ bg) {
    extern __shared__ uint32_t smd[];
    uint32_t* sm = smd;
    float* ys = reinterpret_cast<float*>(smd + 3 * STGW);
    uint32_t sbase = (uint32_t)__cvta_generic_to_shared(sm);
    int m0 = blockIdx.y * 128;
    int nx = blockIdx.x;
    int cb = nx * 128;
    int tid = threadIdx.x;
    int lane = tid & 31, wid = tid >> 5;
    int wm = wid >> 2, wn = wid & 3;
    int group = lane >> 2, tid4 = lane & 3;

    float acc[4][4][4];
    gemm_pipe(sm, sbase, &g_old[(size_t)m0 * KDIM],
              &g_wgt[(size_t)(NBM + cb) * KDIM], tid, acc);

    int nidx = (cb + wn * 32) >> 6;
    const float* bgp = &bg[DEL + NBM + cb + wn * 32];
    int sbase_s = (wn * 32) & 63;

    float yv[4][4][4];
    #pragma unroll
    for (int mt = 0; mt < 4; mt++) {
        int r0 = m0 + wm * 64 + mt * 16 + group;
        float z0 = g_z[r0 * N_ + nidx];
        float z1 = g_z[(r0 + 8) * N_ + nidx];
        #pragma unroll
        for (int nt = 0; nt < 4; nt++) {
            int cc = nt * 8 + tid4 * 2;
            float bg0 = bgp[cc], bg1 = bgp[cc + 1];
            yv[mt][nt][0] = (acc[mt][nt][0] + bg0) * z0;
            yv[mt][nt][1] = (acc[mt][nt][1] + bg1) * z0;
            yv[mt][nt][2] = (acc[mt][nt][2] + bg0) * z1;
            yv[mt][nt][3] = (acc[mt][nt][3] + bg1) * z1;
        }
    }

    __syncthreads();

    if (wn < 2) {
        #pragma unroll
        for (int mt = 0; mt < 4; mt++) {
            int lr = wm * 64 + mt * 16 + group;
            #pragma unroll
            for (int nt = 0; nt < 4; nt++) {
                int s = sbase_s + nt * 8 + tid4 * 2;
                ys[lr * YSW + s]       = yv[mt][nt][0];
                ys[lr * YSW + s + 1]   = yv[mt][nt][1];
                ys[(lr + 8) * YSW + s]     = yv[mt][nt][2];
                ys[(lr + 8) * YSW + s + 1] = yv[mt][nt][3];
            }
        }
    }
    __syncthreads();
    if (wn >= 2) {
        #pragma unroll
        for (int mt = 0; mt < 4; mt++) {
            int lr = wm * 64 + mt * 16 + group;
            #pragma unroll
            for (int nt = 0; nt < 4; nt++) {
                int s = sbase_s + nt * 8 + tid4 * 2;
                ys[lr * YSW + s]       += yv[mt][nt][0];
                ys[lr * YSW + s + 1]   += yv[mt][nt][1];
                ys[(lr + 8) * YSW + s]     += yv[mt][nt][2];
                ys[(lr + 8) * YSW + s + 1] += yv[mt][nt][3];
            }
        }
    }
    __syncthreads();

    float* slice = &g_ys[((size_t)nx * TOK + m0) * S_];
    for (int i = tid; i < 128 * 64; i += 256) {
        int r = i >> 6, s = i & 63;
        slice[r * S_ + s] = ys[r * YSW + s];
    }
}

// ------------------------------------------------------------------
// K8: y finalize: sum 128 slices, write ys output + mse partial.
// ------------------------------------------------------------------
__global__ void k_yfin(const float* __restrict__ x, float* __restrict__ out) {
    __shared__ float red[2];
    int tok = blockIdx.x;
    int b = tok >> 7, t = tok & 127;
    int s = threadIdx.x;   // 0..63
    const float* base = &g_ys[(size_t)tok * S_ + s];
    float yv = 0.0f;
    #pragma unroll 8
    for (int n = 0; n < NYT; n++) yv += base[(size_t)n * TOK * S_];
    out[1 + ((t << 4) + b) * S_ + s] = yv;
    float diff = yv - x[(b * 256 + 128 + t) * S_ + s];
    float v = diff * diff;
    #pragma unroll
    for (int o = 16; o > 0; o >>= 1) v += __shfl_down_sync(0xffffffffu, v, o);
    if ((s & 31) == 0) red[s >> 5] = v;
    __syncthreads();
    if (s == 0) g_part[tok] = red[0] + red[1];
}

// ------------------------------------------------------------------
// K9: loss reduction.
// ------------------------------------------------------------------
__global__ void k_loss(float* __restrict__ out) {
    __shared__ float red[256];
    float v = 0.0f;
    for (int i = threadIdx.x; i < TOK; i += 256) v += g_part[i];
    red[threadIdx.x] = v;
    __syncthreads();
    for (int st = 128; st > 0; st >>= 1) {
        if (threadIdx.x < st) red[threadIdx.x] += red[threadIdx.x + st];
        __syncthreads();
    }
    if (threadIdx.x == 0) out[0] = red[0] / (float)(B_ * S_ * L_);
}

// ------------------------------------------------------------------
// Launch with stream-level overlap (fork/join via events; capture-safe).
// Dep graph:  proj -> conv -> {delta(s2, after wcomb), bu(main, after wround)}
//             -> scan -> y -> yfin -> loss
// wround(s1) and wcomb(s2) run concurrently with proj+conv.
// ------------------------------------------------------------------
extern "C" void kernel_launch(void* const* d_in, const int* in_sizes, int n_in,
                              void* d_out, int out_size) {
    const float* x   = (const float*)d_in[0];
    const float* u   = (const float*)d_in[1];
    const float* A   = (const float*)d_in[2];
    const float* W0  = (const float*)d_in[3];
    const float* b0  = (const float*)d_in[4];
    const float* W1  = (const float*)d_in[5];
    const float* b1  = (const float*)d_in[6];
    const float* cw  = (const float*)d_in[7];
    const float* cb  = (const float*)d_in[8];
    const float* Wg  = (const float*)d_in[9];
    const float* bg  = (const float*)d_in[10];
    const float* Wdt = (const float*)d_in[11];
    const float* bdt = (const float*)d_in[12];
    float* out = (float*)d_out;

    static cudaStream_t s1 = nullptr, s2 = nullptr;
    static cudaEvent_t ev0, ev1, ev2, evConv;
    static int init_done = 0;
    if (!init_done) {
        cudaStreamCreateWithFlags(&s1, cudaStreamNonBlocking);
        cudaStreamCreateWithFlags(&s2, cudaStreamNonBlocking);
        cudaEventCreateWithFlags(&ev0,    cudaEventDisableTiming);
        cudaEventCreateWithFlags(&ev1,    cudaEventDisableTiming);
        cudaEventCreateWithFlags(&ev2,    cudaEventDisableTiming);
        cudaEventCreateWithFlags(&evConv, cudaEventDisableTiming);
        cudaFuncSetAttribute(k_gemm_y, cudaFuncAttributeMaxDynamicSharedMemorySize,
                             GSMEM_Y);
        init_done = 1;
    }

    // fork
    cudaEventRecord(ev0, 0);
    cudaStreamWaitEvent(s1, ev0, 0);
    cudaStreamWaitEvent(s2, ev0, 0);

    // side stream 1: weight conversion (pure DRAM)
    k_wround<<<1024, 256, 0, s1>>>(Wg);
    cudaEventRecord(ev1, s1);

    // side stream 2: combined delta weights, then (after conv) delta GEMM
    k_wcomb<<<N_, CDIM, 0, s2>>>(Wg, bg, Wdt, bdt);

    // main stream: proj -> conv
    k_proj<<<256, 256>>>(x, W0, b0, W1, b1);
    k_conv<<<TOK, CDIM>>>(u, cw, cb);
    cudaEventRecord(evConv, 0);

    // delta GEMM on s2 (after wcomb by stream order, after conv by event);
    // runs concurrently with the Bm GEMM below.
    cudaStreamWaitEvent(s2, evConv, 0);
    k_gemm_delta<<<dim3(2, 16), 256, 0, s2>>>();
    cudaEventRecord(ev2, s2);

    // main: Bm GEMM (needs wround)
    cudaStreamWaitEvent(0, ev1, 0);
    k_gemm_bu<<<dim3(NBM / 128, 16), 256>>>(bg, u);

    // join delta, then scan -> y -> finalize
    cudaStreamWaitEvent(0, ev2, 0);
    k_scan<<<128, 32>>>(A);
    k_gemm_y<<<dim3(NYT, 16), 256, GSMEM_Y>>>(bg);
    k_yfin<<<TOK, S_>>>(x, out);
    k_loss<<<1, 256>>>(out);
}

// round 16
// speedup vs baseline: 1.7108x; 1.7108x over previous
#include <cuda_runtime.h>
#include <cuda_fp16.h>
#include <math.h>
#include <stdint.h>

// ---- problem constants ----
#define B_   16
#define L_   128
#define O_   128
#define N_   256
#define S_   64
#define U_   32
#define DEL  64
#define HID  512
#define KC   4
#define CDIM 288           // N_ + U_
#define TOK  2048          // B_ * L_
#define KDIM 288
#define NBM  8192          // N_*U_  (Bm cols)
#define NCM  16384         // N_*S_  (Cm cols)
#define WROWS (NBM + NCM)  // 24576 fp16 Wg rows (starting at DEL)
#define NYT  128           // y n-tiles (NCM/128)

// ---- scratch (device globals) ----
__device__ __align__(16) float  g_p[TOK * N_];
__device__ __align__(16) __half g_old[TOK * CDIM];
__device__ __align__(16) __half g_wgt[(size_t)WROWS * KDIM];  // fp16 Wg[64:]
__device__ __align__(16) __half g_wc[N_ * KDIM];
__device__ float g_bc[N_];
__device__ __align__(16) float g_dpre[TOK * N_];
__device__ float g_buraw[TOK * N_];
__device__ float g_z[TOK * N_];
__device__ __align__(16) float g_ys[(size_t)NYT * TOK * S_];  // per-ntile y slices
__device__ float g_part[TOK];

__device__ __forceinline__ float siluf(float v) { return v / (1.0f + expf(-v)); }

__device__ __forceinline__ void mma16(float* c, const uint32_t* a, const uint32_t* b) {
    asm volatile("mma.sync.aligned.m16n8k16.row.col.f32.f16.f16.f32 "
        "{%0,%1,%2,%3}, {%4,%5,%6,%7}, {%8,%9}, {%0,%1,%2,%3};"
        : "+f"(c[0]), "+f"(c[1]), "+f"(c[2]), "+f"(c[3])
        : "r"(a[0]), "r"(a[1]), "r"(a[2]), "r"(a[3]), "r"(b[0]), "r"(b[1]));
}
__device__ __forceinline__ void ldsm4(uint32_t* r, uint32_t addr) {
    asm volatile("ldmatrix.sync.aligned.m8n8.x4.shared.b16 {%0,%1,%2,%3}, [%4];"
        : "=r"(r[0]), "=r"(r[1]), "=r"(r[2]), "=r"(r[3]) : "r"(addr));
}
__device__ __forceinline__ void cp16(uint32_t d, const void* s) {
    asm volatile("cp.async.cg.shared.global [%0], [%1], 16;"
                 :: "r"(d), "l"(__cvta_generic_to_global(s)));
}
#define CPCOMMIT() asm volatile("cp.async.commit_group;" ::: "memory")
#define CPWAIT1()  asm volatile("cp.async.wait_group 1;" ::: "memory")
#define CPWAIT0()  asm volatile("cp.async.wait_group 0;" ::: "memory")

// ------------------------------------------------------------------
// 3-stage fp16 GEMM tile: BM=128, BN=128, BK=32 halves, K=288 (9 iters).
// SMEM: stage s at s*4096 words: A (128 rows x 16 words) then B.
// Swizzle (bytes): row r, 16B-chunk c -> r*64 + (c ^ ((r>>1)&3))*16
// Fragments gathered via ldmatrix.m8n8.x4 (12 per iter vs 48 scalar LDS):
//   A tile mt: matrices {m-lo/k-lo, m-hi/k-lo, m-lo/k-hi, m-hi/k-hi}
//   B pair pp: matrices {n(2pp)/k-lo, n(2pp)/k-hi, n(2pp+1)/k-lo, n(2pp+1)/k-hi}
// C fragment layout unchanged:
//  rows r0 = m0 + (wid>>2)*64 + mt*16 + (lane>>2), r0+8   (mt 0..3)
//  cols c  = (wid&3)*32 + nt*8 + (lane&3)*2, c+1           (nt 0..3)
// ------------------------------------------------------------------
#define STGW 4096   // words per stage (16 KB)

__device__ __forceinline__ void pipe_issue(uint32_t sbase, int stage,
                                           const __half* __restrict__ Aptr,
                                           const __half* __restrict__ Bptr,
                                           int k0, int tid) {
    uint32_t aB = sbase + (uint32_t)stage * STGW * 4u;
    uint32_t bB = aB + 2048u * 4u;
    #pragma unroll
    for (int p = 0; p < 2; p++) {
        int idx = tid + p * 256;
        int r = idx >> 2, c0 = idx & 3;
        uint32_t off = (uint32_t)(r * 16 + ((c0 ^ ((r >> 1) & 3)) << 2)) * 4u;
        cp16(aB + off, Aptr + (size_t)r * KDIM + k0 + c0 * 8);
        cp16(bB + off, Bptr + (size_t)r * KDIM + k0 + c0 * 8);
    }
}

__device__ __forceinline__ void gemm_pipe(uint32_t* sm, uint32_t sbase,
                                          const __half* __restrict__ Aptr,
                                          const __half* __restrict__ Bptr,
                                          int tid, float acc[4][4][4]) {
    int lane = tid & 31, wid = tid >> 5;
    int wm = wid >> 2, wn = wid & 3;
    int mBase = wm * 64, nBase = wn * 32;

    // per-lane ldmatrix address components
    int mid  = lane >> 3;              // matrix slot 0..3
    int arof = ((mid & 1) << 3) | (lane & 7);   // A row-in-tile
    int aq   = mid >> 1;                         // A k-chunk parity
    int bnt  = mid >> 1;                         // B nt-within-pair
    int bq   = mid & 1;                          // B k-chunk parity
    uint32_t aoff[4], aswz[4];
    #pragma unroll
    for (int mt = 0; mt < 4; mt++) {
        int r = mBase + mt * 16 + arof;
        aoff[mt] = (uint32_t)r * 64u;
        aswz[mt] = (uint32_t)((r >> 1) & 3);
    }
    uint32_t boff[2], bswz[2];
    #pragma unroll
    for (int pp = 0; pp < 2; pp++) {
        int n = nBase + ((pp << 1) + bnt) * 8 + (lane & 7);
        boff[pp] = (uint32_t)n * 64u;
        bswz[pp] = (uint32_t)((n >> 1) & 3);
    }

    #pragma unroll
    for (int i = 0; i < 4; i++)
        #pragma unroll
        for (int j = 0; j < 4; j++)
            #pragma unroll
            for (int q = 0; q < 4; q++) acc[i][j][q] = 0.0f;

    pipe_issue(sbase, 0, Aptr, Bptr, 0, tid);
    CPCOMMIT();
    pipe_issue(sbase, 1, Aptr, Bptr, 32, tid);
    CPCOMMIT();

    #pragma unroll 1
    for (int it = 0; it < 9; it++) {
        if (it < 8) { CPWAIT1(); } else { CPWAIT0(); }
        __syncthreads();
        if (it + 2 < 9) {
            pipe_issue(sbase, (it + 2) % 3, Aptr, Bptr, (it + 2) * 32, tid);
            CPCOMMIT();
        }

        uint32_t aB = sbase + (uint32_t)(it % 3) * STGW * 4u;
        uint32_t bB = aB + 8192u;

        #pragma unroll
        for (int ks = 0; ks < 2; ks++) {
            uint32_t af[4][4], bf[4][2];
            #pragma unroll
            for (int mt = 0; mt < 4; mt++) {
                uint32_t ad = aB + aoff[mt] + ((((uint32_t)(2 * ks) + aq) ^ aswz[mt]) << 4);
                ldsm4(af[mt], ad);
            }
            #pragma unroll
            for (int pp = 0; pp < 2; pp++) {
                uint32_t regs[4];
                uint32_t bd = bB + boff[pp] + ((((uint32_t)(2 * ks) + bq) ^ bswz[pp]) << 4);
                ldsm4(regs, bd);
                bf[2 * pp][0] = regs[0];     bf[2 * pp][1] = regs[1];
                bf[2 * pp + 1][0] = regs[2]; bf[2 * pp + 1][1] = regs[3];
            }
            #pragma unroll
            for (int mt = 0; mt < 4; mt++)
                #pragma unroll
                for (int nt = 0; nt < 4; nt++)
                    mma16(acc[mt][nt], af[mt], bf[nt]);
        }
    }
}

// ------------------------------------------------------------------
// K1: proj_x
// ------------------------------------------------------------------
__global__ void __launch_bounds__(256) k_proj(const float* __restrict__ x,
                                              const float* __restrict__ W0,
                                              const float* __restrict__ b0,
                                              const float* __restrict__ W1,
                                              const float* __restrict__ b1) {
    __shared__ float xs[8][64];
    __shared__ float hs[8][512];
    int b  = blockIdx.x >> 4;
    int t0 = (blockIdx.x & 15) * 8;
    int tid = threadIdx.x;

    for (int i = tid; i < 8 * 64; i += 256) {
        int tt = i >> 6, k = i & 63;
        xs[tt][k] = x[(b * (O_ + L_) + t0 + tt) * S_ + k];
    }
    __syncthreads();

    #pragma unroll
    for (int jj = 0; jj < 2; jj++) {
        int j = tid + jj * 256;
        float acc[8];
        float bj = b0[j];
        #pragma unroll
        for (int tt = 0; tt < 8; tt++) acc[tt] = bj;
        for (int k = 0; k < 64; k++) {
            float w = W0[j * 64 + k];
            #pragma unroll
            for (int tt = 0; tt < 8; tt++) acc[tt] += w * xs[tt][k];
        }
        #pragma unroll
        for (int tt = 0; tt < 8; tt++) hs[tt][j] = fmaxf(acc[tt], 0.0f);
    }
    __syncthreads();

    int n = tid;
    float acc2[8];
    float bn = b1[n];
    #pragma unroll
    for (int tt = 0; tt < 8; tt++) acc2[tt] = bn;
    for (int j = 0; j < 512; j++) {
        float w = W1[n * 512 + j];
        #pragma unroll
        for (int tt = 0; tt < 8; tt++) acc2[tt] += w * hs[tt][j];
    }
    #pragma unroll
    for (int tt = 0; tt < 8; tt++) g_p[(b * L_ + t0 + tt) * N_ + n] = acc2[tt];
}

// ------------------------------------------------------------------
// K2: silu -> depthwise conv -> silu, output fp16.
// ------------------------------------------------------------------
__global__ void k_conv(const float* __restrict__ u,
                       const float* __restrict__ cw,
                       const float* __restrict__ cb) {
    int tok = blockIdx.x;
    int b = tok >> 7, l = tok & 127;
    int c = threadIdx.x;   // 0..287
    float acc = cb[c];
    #pragma unroll
    for (int k = 0; k < KC; k++) {
        int i = l - 1 + k;
        if (i >= 0 && i <= 126) {
            float v = (c < 256) ? g_p[((b << 7) + i) * N_ + c]
                                : u[(b * 256 + i) * U_ + (c - 256)];
            acc += cw[c * 4 + k] * siluf(v);
        }
    }
    g_old[tok * CDIM + c] = __float2half_rn(siluf(acc));
}

// ------------------------------------------------------------------
// K3a: fp16-convert Wg rows DEL.. into g_wgt.
// ------------------------------------------------------------------
struct h4pack { __half2 a, b; };
__global__ void k_wround(const float* __restrict__ Wg) {
    const float4* src = reinterpret_cast<const float4*>(Wg + (size_t)DEL * KDIM);
    h4pack* dst = reinterpret_cast<h4pack*>(g_wgt);
    int total = (WROWS * KDIM) / 4;
    for (int i = blockIdx.x * blockDim.x + threadIdx.x; i < total;
         i += gridDim.x * blockDim.x) {
        float4 v = src[i];
        h4pack o;
        o.a = __floats2half2_rn(v.x, v.y);
        o.b = __floats2half2_rn(v.z, v.w);
        dst[i] = o;
    }
}

// ------------------------------------------------------------------
// K3b: Wc = Wdt @ Wg[0:64] (fp16), bc.
// ------------------------------------------------------------------
__global__ void k_wcomb(const float* __restrict__ Wg, const float* __restrict__ bg,
                        const float* __restrict__ Wdt, const float* __restrict__ bdt) {
    __shared__ float sw[64];
    int n = blockIdx.x;       // 0..255
    int tid = threadIdx.x;    // 0..287
    if (tid < 64) sw[tid] = Wdt[n * 64 + tid];
    __syncthreads();
    float acc = 0.0f;
    #pragma unroll 8
    for (int d = 0; d < 64; d++) acc += sw[d] * Wg[d * KDIM + tid];
    g_wc[n * KDIM + tid] = __float2half_rn(acc);
    if (tid == 0) {
        float s = bdt[n];
        for (int d = 0; d < 64; d++) s += sw[d] * bg[d];
        g_bc[n] = s;
    }
}

// ------------------------------------------------------------------
// K4: delta GEMM: g_dpre = old @ Wc^T  (M=2048, N=256)
// ------------------------------------------------------------------
__global__ void __launch_bounds__(256, 2) k_gemm_delta() {
    __shared__ uint32_t sm[3 * STGW];
    uint32_t sbase = (uint32_t)__cvta_generic_to_shared(sm);
    int m0 = blockIdx.y * 128;
    int n0 = blockIdx.x * 128;
    int tid = threadIdx.x;
    int lane = tid & 31, wid = tid >> 5;
    int wm = wid >> 2, wn = wid & 3;
    int group = lane >> 2, tid4 = lane & 3;

    float acc[4][4][4];
    gemm_pipe(sm, sbase, &g_old[(size_t)m0 * KDIM], &g_wc[(size_t)n0 * KDIM], tid, acc);

    #pragma unroll
    for (int mt = 0; mt < 4; mt++) {
        int r0 = m0 + wm * 64 + mt * 16 + group;
        #pragma unroll
        for (int nt = 0; nt < 4; nt++) {
            int c = n0 + wn * 32 + nt * 8 + tid4 * 2;
            *reinterpret_cast<float2*>(&g_dpre[r0 * N_ + c]) =
                make_float2(acc[mt][nt][0], acc[mt][nt][1]);
            *reinterpret_cast<float2*>(&g_dpre[(r0 + 8) * N_ + c]) =
                make_float2(acc[mt][nt][2], acc[mt][nt][3]);
        }
    }
}

// ------------------------------------------------------------------
// K5: Bm GEMM + fused Bu epilogue. BN=128: warp wn owns one n (32 u-cols).
// ------------------------------------------------------------------
__global__ void __launch_bounds__(256, 2) k_gemm_bu(const float* __restrict__ bg,
                                                    const float* __restrict__ u) {
    __shared__ uint32_t sm[3 * STGW];
    uint32_t sbase = (uint32_t)__cvta_generic_to_shared(sm);
    int m0 = blockIdx.y * 128;
    int n0 = blockIdx.x * 128;     // local Bm col
    int tid = threadIdx.x;
    int lane = tid & 31, wid = tid >> 5;
    int wm = wid >> 2, wn = wid & 3;
    int group = lane >> 2, tid4 = lane & 3;

    float acc[4][4][4];
    gemm_pipe(sm, sbase, &g_old[(size_t)m0 * KDIM], &g_wgt[(size_t)n0 * KDIM], tid, acc);

    int nb = blockIdx.x * 4 + wn;
    const float* bgp = &bg[DEL + n0 + wn * 32];

    #pragma unroll
    for (int mt = 0; mt < 4; mt++) {
        int r0 = m0 + wm * 64 + mt * 16 + group;
        int r1 = r0 + 8;
        const float* u0p = &u[((r0 >> 7) * 256 + 127 + (r0 & 127)) * U_];
        const float* u1p = &u[((r1 >> 7) * 256 + 127 + (r1 & 127)) * U_];
        float s0 = 0.0f, s1 = 0.0f;
        #pragma unroll
        for (int nt = 0; nt < 4; nt++) {
            int uu = nt * 8 + tid4 * 2;
            float bg0 = bgp[uu], bg1 = bgp[uu + 1];
            s0 += (acc[mt][nt][0] + bg0) * u0p[uu] + (acc[mt][nt][1] + bg1) * u0p[uu + 1];
            s1 += (acc[mt][nt][2] + bg0) * u1p[uu] + (acc[mt][nt][3] + bg1) * u1p[uu + 1];
        }
        s0 += __shfl_xor_sync(0xffffffffu, s0, 1);
        s0 += __shfl_xor_sync(0xffffffffu, s0, 2);
        s1 += __shfl_xor_sync(0xffffffffu, s1, 1);
        s1 += __shfl_xor_sync(0xffffffffu, s1, 2);
        if (tid4 == 0) {
            g_buraw[r0 * N_ + nb] = s0;
            g_buraw[r1 * N_ + nb] = s1;
        }
    }
}

// ------------------------------------------------------------------
// K6: fused delta-transform + sequential scan (128 blocks x 32 threads).
// ------------------------------------------------------------------
__global__ void __launch_bounds__(32) k_scan(const float* __restrict__ A) {
    int b = blockIdx.x >> 3;
    int n = ((blockIdx.x & 7) << 5) + threadIdx.x;
    float a = A[n];
    float an = (a > 0.0f) ? -a : -expm1f(a);
    float inv_an = 1.0f / an;
    float bcn = g_bc[n];
    float z = g_p[((b << 7) + 127) * N_ + n];
    for (int t0 = 0; t0 < L_; t0 += 8) {
        float dp[8], bu[8], da[8], cb[8];
        #pragma unroll
        for (int q = 0; q < 8; q++) {
            int idx = ((b << 7) + t0 + q) * N_ + n;
            dp[q] = g_dpre[idx];
            bu[q] = g_buraw[idx];
        }
        #pragma unroll
        for (int q = 0; q < 8; q++) {
            float acc = dp[q] + bcn;
            float sp = fmaxf(acc, 0.0f) + log1pf(expf(-fabsf(acc)));
            da[q] = expf(sp * an);
            cb[q] = (da[q] - 1.0f) * inv_an * bu[q];
        }
        #pragma unroll
        for (int q = 0; q < 8; q++) {
            z = z * da[q] + cb[q];
            g_z[((b << 7) + t0 + q) * N_ + n] = z;
        }
    }
}

// ------------------------------------------------------------------
// K7: Cm GEMM + fused y epilogue. Two-phase smem reduction into
// padded ys[128][65], plain stores to per-ntile slice (no atomics).
// ------------------------------------------------------------------
#define YSW 65
#define GSMEM_Y (3 * STGW * 4 + 128 * YSW * 4)

__global__ void __launch_bounds__(256, 2) k_gemm_y(const float* __restrict__ bg) {
    extern __shared__ uint32_t smd[];
    uint32_t* sm = smd;
    float* ys = reinterpret_cast<float*>(smd + 3 * STGW);
    uint32_t sbase = (uint32_t)__cvta_generic_to_shared(sm);
    int m0 = blockIdx.y * 128;
    int nx = blockIdx.x;
    int cb = nx * 128;
    int tid = threadIdx.x;
    int lane = tid & 31, wid = tid >> 5;
    int wm = wid >> 2, wn = wid & 3;
    int group = lane >> 2, tid4 = lane & 3;

    float acc[4][4][4];
    gemm_pipe(sm, sbase, &g_old[(size_t)m0 * KDIM],
              &g_wgt[(size_t)(NBM + cb) * KDIM], tid, acc);

    int nidx = (cb + wn * 32) >> 6;
    const float* bgp = &bg[DEL + NBM + cb + wn * 32];
    int sbase_s = (wn * 32) & 63;

    float yv[4][4][4];
    #pragma unroll
    for (int mt = 0; mt < 4; mt++) {
        int r0 = m0 + wm * 64 + mt * 16 + group;
        float z0 = g_z[r0 * N_ + nidx];
        float z1 = g_z[(r0 + 8) * N_ + nidx];
        #pragma unroll
        for (int nt = 0; nt < 4; nt++) {
            int cc = nt * 8 + tid4 * 2;
            float bg0 = bgp[cc], bg1 = bgp[cc + 1];
            yv[mt][nt][0] = (acc[mt][nt][0] + bg0) * z0;
            yv[mt][nt][1] = (acc[mt][nt][1] + bg1) * z0;
            yv[mt][nt][2] = (acc[mt][nt][2] + bg0) * z1;
            yv[mt][nt][3] = (acc[mt][nt][3] + bg1) * z1;
        }
    }

    __syncthreads();

    if (wn < 2) {
        #pragma unroll
        for (int mt = 0; mt < 4; mt++) {
            int lr = wm * 64 + mt * 16 + group;
            #pragma unroll
            for (int nt = 0; nt < 4; nt++) {
                int s = sbase_s + nt * 8 + tid4 * 2;
                ys[lr * YSW + s]       = yv[mt][nt][0];
                ys[lr * YSW + s + 1]   = yv[mt][nt][1];
                ys[(lr + 8) * YSW + s]     = yv[mt][nt][2];
                ys[(lr + 8) * YSW + s + 1] = yv[mt][nt][3];
            }
        }
    }
    __syncthreads();
    if (wn >= 2) {
        #pragma unroll
        for (int mt = 0; mt < 4; mt++) {
            int lr = wm * 64 + mt * 16 + group;
            #pragma unroll
            for (int nt = 0; nt < 4; nt++) {
                int s = sbase_s + nt * 8 + tid4 * 2;
                ys[lr * YSW + s]       += yv[mt][nt][0];
                ys[lr * YSW + s + 1]   += yv[mt][nt][1];
                ys[(lr + 8) * YSW + s]     += yv[mt][nt][2];
                ys[(lr + 8) * YSW + s + 1] += yv[mt][nt][3];
            }
        }
    }
    __syncthreads();

    float* slice = &g_ys[((size_t)nx * TOK + m0) * S_];
    for (int i = tid; i < 128 * 64; i += 256) {
        int r = i >> 6, s = i & 63;
        slice[r * S_ + s] = ys[r * YSW + s];
    }
}

// ------------------------------------------------------------------
// K8: y finalize: sum 128 slices, write ys output + mse partial.
// ------------------------------------------------------------------
__global__ void k_yfin(const float* __restrict__ x, float* __restrict__ out) {
    __shared__ float red[2];
    int tok = blockIdx.x;
    int b = tok >> 7, t = tok & 127;
    int s = threadIdx.x;   // 0..63
    const float* base = &g_ys[(size_t)tok * S_ + s];
    float yv = 0.0f;
    #pragma unroll 8
    for (int n = 0; n < NYT; n++) yv += base[(size_t)n * TOK * S_];
    out[1 + ((t << 4) + b) * S_ + s] = yv;
    float diff = yv - x[(b * 256 + 128 + t) * S_ + s];
    float v = diff * diff;
    #pragma unroll
    for (int o = 16; o > 0; o >>= 1) v += __shfl_down_sync(0xffffffffu, v, o);
    if ((s & 31) == 0) red[s >> 5] = v;
    __syncthreads();
    if (s == 0) g_part[tok] = red[0] + red[1];
}

// ------------------------------------------------------------------
// K9: loss reduction.
// ------------------------------------------------------------------
__global__ void k_loss(float* __restrict__ out) {
    __shared__ float red[256];
    float v = 0.0f;
    for (int i = threadIdx.x; i < TOK; i += 256) v += g_part[i];
    red[threadIdx.x] = v;
    __syncthreads();
    for (int st = 128; st > 0; st >>= 1) {
        if (threadIdx.x < st) red[threadIdx.x] += red[threadIdx.x + st];
        __syncthreads();
    }
    if (threadIdx.x == 0) out[0] = red[0] / (float)(B_ * S_ * L_);
}

// ------------------------------------------------------------------
// Single linear stream (stream forking regressed under graph capture).
// ------------------------------------------------------------------
extern "C" void kernel_launch(void* const* d_in, const int* in_sizes, int n_in,
                              void* d_out, int out_size) {
    const float* x   = (const float*)d_in[0];
    const float* u   = (const float*)d_in[1];
    const float* A   = (const float*)d_in[2];
    const float* W0  = (const float*)d_in[3];
    const float* b0  = (const float*)d_in[4];
    const float* W1  = (const float*)d_in[5];
    const float* b1  = (const float*)d_in[6];
    const float* cw  = (const float*)d_in[7];
    const float* cb  = (const float*)d_in[8];
    const float* Wg  = (const float*)d_in[9];
    const float* bg  = (const float*)d_in[10];
    const float* Wdt = (const float*)d_in[11];
    const float* bdt = (const float*)d_in[12];
    float* out = (float*)d_out;

    cudaFuncSetAttribute(k_gemm_y, cudaFuncAttributeMaxDynamicSharedMemorySize, GSMEM_Y);

    k_proj<<<256, 256>>>(x, W0, b0, W1, b1);
    k_conv<<<TOK, CDIM>>>(u, cw, cb);
    k_wround<<<1024, 256>>>(Wg);
    k_wcomb<<<N_, CDIM>>>(Wg, bg, Wdt, bdt);
    k_gemm_delta<<<dim3(2, 16), 256>>>();
    k_gemm_bu<<<dim3(NBM / 128, 16), 256>>>(bg, u);
    k_scan<<<128, 32>>>(A);
    k_gemm_y<<<dim3(NYT, 16), 256, GSMEM_Y>>>(bg);
    k_yfin<<<TOK, S_>>>(x, out);
    k_loss<<<1, 256>>>(out);
}

// round 17
// speedup vs baseline: 1.7196x; 1.0052x over previous
#include <cuda_runtime.h>
#include <cuda_fp16.h>
#include <math.h>
#include <stdint.h>

// ---- problem constants ----
#define B_   16
#define L_   128
#define O_   128
#define N_   256
#define S_   64
#define U_   32
#define DEL  64
#define HID  512
#define KC   4
#define CDIM 288           // N_ + U_
#define TOK  2048          // B_ * L_
#define KDIM 288
#define NBM  8192          // N_*U_  (Bm cols)
#define NCM  16384         // N_*S_  (Cm cols)
#define WROWS (NBM + NCM)  // 24576 fp16 Wg rows (starting at DEL)
#define NYT  128           // y n-tiles (NCM/128)

// ---- scratch (device globals) ----
__device__ __align__(16) float  g_p[TOK * N_];
__device__ __align__(16) __half g_old[TOK * CDIM];
__device__ __align__(16) __half g_wgt[(size_t)WROWS * KDIM];  // fp16 Wg[64:]
__device__ __align__(16) __half g_wc[N_ * KDIM];
__device__ float g_bc[N_];
__device__ __align__(16) float g_dpre[TOK * N_];   // dpre -> (in place) dA
__device__ float g_buraw[TOK * N_];                // buraw -> (in place) coeff*bu
__device__ float g_z[TOK * N_];
__device__ __align__(16) float g_ys[(size_t)NYT * TOK * S_];  // per-ntile y slices
__device__ float g_part[TOK];

__device__ __forceinline__ float siluf(float v) { return v / (1.0f + expf(-v)); }

__device__ __forceinline__ void mma16(float* c, const uint32_t* a, const uint32_t* b) {
    asm volatile("mma.sync.aligned.m16n8k16.row.col.f32.f16.f16.f32 "
        "{%0,%1,%2,%3}, {%4,%5,%6,%7}, {%8,%9}, {%0,%1,%2,%3};"
        : "+f"(c[0]), "+f"(c[1]), "+f"(c[2]), "+f"(c[3])
        : "r"(a[0]), "r"(a[1]), "r"(a[2]), "r"(a[3]), "r"(b[0]), "r"(b[1]));
}
__device__ __forceinline__ void ldsm4(uint32_t* r, uint32_t addr) {
    asm volatile("ldmatrix.sync.aligned.m8n8.x4.shared.b16 {%0,%1,%2,%3}, [%4];"
        : "=r"(r[0]), "=r"(r[1]), "=r"(r[2]), "=r"(r[3]) : "r"(addr));
}
__device__ __forceinline__ void cp16(uint32_t d, const void* s) {
    asm volatile("cp.async.cg.shared.global [%0], [%1], 16;"
                 :: "r"(d), "l"(__cvta_generic_to_global(s)));
}
#define CPCOMMIT() asm volatile("cp.async.commit_group;" ::: "memory")
#define CPWAIT1()  asm volatile("cp.async.wait_group 1;" ::: "memory")
#define CPWAIT0()  asm volatile("cp.async.wait_group 0;" ::: "memory")

// ------------------------------------------------------------------
// 3-stage fp16 GEMM tile: BM=128, BN=128, BK=32 halves, K=288 (9 iters).
// SMEM: stage s at s*4096 words: A (128 rows x 16 words) then B.
// Swizzle (bytes): row r, 16B-chunk c -> r*64 + (c ^ ((r>>1)&3))*16
// Fragments gathered via ldmatrix.m8n8.x4 (12 per iter).
// C fragment layout:
//  rows r0 = m0 + (wid>>2)*64 + mt*16 + (lane>>2), r0+8   (mt 0..3)
//  cols c  = (wid&3)*32 + nt*8 + (lane&3)*2, c+1           (nt 0..3)
// ------------------------------------------------------------------
#define STGW 4096   // words per stage (16 KB)

__device__ __forceinline__ void pipe_issue(uint32_t sbase, int stage,
                                           const __half* __restrict__ Aptr,
                                           const __half* __restrict__ Bptr,
                                           int k0, int tid) {
    uint32_t aB = sbase + (uint32_t)stage * STGW * 4u;
    uint32_t bB = aB + 2048u * 4u;
    #pragma unroll
    for (int p = 0; p < 2; p++) {
        int idx = tid + p * 256;
        int r = idx >> 2, c0 = idx & 3;
        uint32_t off = (uint32_t)(r * 16 + ((c0 ^ ((r >> 1) & 3)) << 2)) * 4u;
        cp16(aB + off, Aptr + (size_t)r * KDIM + k0 + c0 * 8);
        cp16(bB + off, Bptr + (size_t)r * KDIM + k0 + c0 * 8);
    }
}

__device__ __forceinline__ void gemm_pipe(uint32_t* sm, uint32_t sbase,
                                          const __half* __restrict__ Aptr,
                                          const __half* __restrict__ Bptr,
                                          int tid, float acc[4][4][4]) {
    int lane = tid & 31, wid = tid >> 5;
    int wm = wid >> 2, wn = wid & 3;
    int mBase = wm * 64, nBase = wn * 32;

    // per-lane ldmatrix address components
    int mid  = lane >> 3;                        // matrix slot 0..3
    int arof = ((mid & 1) << 3) | (lane & 7);    // A row-in-tile
    int aq   = mid >> 1;                         // A k-chunk parity
    int bnt  = mid >> 1;                         // B nt-within-pair
    int bq   = mid & 1;                          // B k-chunk parity
    uint32_t aoff[4], aswz[4];
    #pragma unroll
    for (int mt = 0; mt < 4; mt++) {
        int r = mBase + mt * 16 + arof;
        aoff[mt] = (uint32_t)r * 64u;
        aswz[mt] = (uint32_t)((r >> 1) & 3);
    }
    uint32_t boff[2], bswz[2];
    #pragma unroll
    for (int pp = 0; pp < 2; pp++) {
        int n = nBase + ((pp << 1) + bnt) * 8 + (lane & 7);
        boff[pp] = (uint32_t)n * 64u;
        bswz[pp] = (uint32_t)((n >> 1) & 3);
    }

    #pragma unroll
    for (int i = 0; i < 4; i++)
        #pragma unroll
        for (int j = 0; j < 4; j++)
            #pragma unroll
            for (int q = 0; q < 4; q++) acc[i][j][q] = 0.0f;

    pipe_issue(sbase, 0, Aptr, Bptr, 0, tid);
    CPCOMMIT();
    pipe_issue(sbase, 1, Aptr, Bptr, 32, tid);
    CPCOMMIT();

    #pragma unroll 1
    for (int it = 0; it < 9; it++) {
        if (it < 8) { CPWAIT1(); } else { CPWAIT0(); }
        __syncthreads();
        if (it + 2 < 9) {
            pipe_issue(sbase, (it + 2) % 3, Aptr, Bptr, (it + 2) * 32, tid);
            CPCOMMIT();
        }

        uint32_t aB = sbase + (uint32_t)(it % 3) * STGW * 4u;
        uint32_t bB = aB + 8192u;

        #pragma unroll
        for (int ks = 0; ks < 2; ks++) {
            uint32_t af[4][4], bf[4][2];
            #pragma unroll
            for (int mt = 0; mt < 4; mt++) {
                uint32_t ad = aB + aoff[mt] + ((((uint32_t)(2 * ks) + aq) ^ aswz[mt]) << 4);
                ldsm4(af[mt], ad);
            }
            #pragma unroll
            for (int pp = 0; pp < 2; pp++) {
                uint32_t regs[4];
                uint32_t bd = bB + boff[pp] + ((((uint32_t)(2 * ks) + bq) ^ bswz[pp]) << 4);
                ldsm4(regs, bd);
                bf[2 * pp][0] = regs[0];     bf[2 * pp][1] = regs[1];
                bf[2 * pp + 1][0] = regs[2]; bf[2 * pp + 1][1] = regs[3];
            }
            #pragma unroll
            for (int mt = 0; mt < 4; mt++)
                #pragma unroll
                for (int nt = 0; nt < 4; nt++)
                    mma16(acc[mt][nt], af[mt], bf[nt]);
        }
    }
}

// ------------------------------------------------------------------
// K1: proj_x
// ------------------------------------------------------------------
__global__ void __launch_bounds__(256) k_proj(const float* __restrict__ x,
                                              const float* __restrict__ W0,
                                              const float* __restrict__ b0,
                                              const float* __restrict__ W1,
                                              const float* __restrict__ b1) {
    __shared__ float xs[8][64];
    __shared__ float hs[8][512];
    int b  = blockIdx.x >> 4;
    int t0 = (blockIdx.x & 15) * 8;
    int tid = threadIdx.x;

    for (int i = tid; i < 8 * 64; i += 256) {
        int tt = i >> 6, k = i & 63;
        xs[tt][k] = x[(b * (O_ + L_) + t0 + tt) * S_ + k];
    }
    __syncthreads();

    #pragma unroll
    for (int jj = 0; jj < 2; jj++) {
        int j = tid + jj * 256;
        float acc[8];
        float bj = b0[j];
        #pragma unroll
        for (int tt = 0; tt < 8; tt++) acc[tt] = bj;
        for (int k = 0; k < 64; k++) {
            float w = W0[j * 64 + k];
            #pragma unroll
            for (int tt = 0; tt < 8; tt++) acc[tt] += w * xs[tt][k];
        }
        #pragma unroll
        for (int tt = 0; tt < 8; tt++) hs[tt][j] = fmaxf(acc[tt], 0.0f);
    }
    __syncthreads();

    int n = tid;
    float acc2[8];
    float bn = b1[n];
    #pragma unroll
    for (int tt = 0; tt < 8; tt++) acc2[tt] = bn;
    for (int j = 0; j < 512; j++) {
        float w = W1[n * 512 + j];
        #pragma unroll
        for (int tt = 0; tt < 8; tt++) acc2[tt] += w * hs[tt][j];
    }
    #pragma unroll
    for (int tt = 0; tt < 8; tt++) g_p[(b * L_ + t0 + tt) * N_ + n] = acc2[tt];
}

// ------------------------------------------------------------------
// K2: silu -> depthwise conv -> silu, output fp16.
// ------------------------------------------------------------------
__global__ void k_conv(const float* __restrict__ u,
                       const float* __restrict__ cw,
                       const float* __restrict__ cb) {
    int tok = blockIdx.x;
    int b = tok >> 7, l = tok & 127;
    int c = threadIdx.x;   // 0..287
    float acc = cb[c];
    #pragma unroll
    for (int k = 0; k < KC; k++) {
        int i = l - 1 + k;
        if (i >= 0 && i <= 126) {
            float v = (c < 256) ? g_p[((b << 7) + i) * N_ + c]
                                : u[(b * 256 + i) * U_ + (c - 256)];
            acc += cw[c * 4 + k] * siluf(v);
        }
    }
    g_old[tok * CDIM + c] = __float2half_rn(siluf(acc));
}

// ------------------------------------------------------------------
// K3a: fp16-convert Wg rows DEL.. into g_wgt.
// ------------------------------------------------------------------
struct h4pack { __half2 a, b; };
__global__ void k_wround(const float* __restrict__ Wg) {
    const float4* src = reinterpret_cast<const float4*>(Wg + (size_t)DEL * KDIM);
    h4pack* dst = reinterpret_cast<h4pack*>(g_wgt);
    int total = (WROWS * KDIM) / 4;
    for (int i = blockIdx.x * blockDim.x + threadIdx.x; i < total;
         i += gridDim.x * blockDim.x) {
        float4 v = src[i];
        h4pack o;
        o.a = __floats2half2_rn(v.x, v.y);
        o.b = __floats2half2_rn(v.z, v.w);
        dst[i] = o;
    }
}

// ------------------------------------------------------------------
// K3b: Wc = Wdt @ Wg[0:64] (fp16), bc.
// ------------------------------------------------------------------
__global__ void k_wcomb(const float* __restrict__ Wg, const float* __restrict__ bg,
                        const float* __restrict__ Wdt, const float* __restrict__ bdt) {
    __shared__ float sw[64];
    int n = blockIdx.x;       // 0..255
    int tid = threadIdx.x;    // 0..287
    if (tid < 64) sw[tid] = Wdt[n * 64 + tid];
    __syncthreads();
    float acc = 0.0f;
    #pragma unroll 8
    for (int d = 0; d < 64; d++) acc += sw[d] * Wg[d * KDIM + tid];
    g_wc[n * KDIM + tid] = __float2half_rn(acc);
    if (tid == 0) {
        float s = bdt[n];
        for (int d = 0; d < 64; d++) s += sw[d] * bg[d];
        g_bc[n] = s;
    }
}

// ------------------------------------------------------------------
// K4: delta GEMM: g_dpre = old @ Wc^T  (M=2048, N=256)
// ------------------------------------------------------------------
__global__ void __launch_bounds__(256, 2) k_gemm_delta() {
    __shared__ uint32_t sm[3 * STGW];
    uint32_t sbase = (uint32_t)__cvta_generic_to_shared(sm);
    int m0 = blockIdx.y * 128;
    int n0 = blockIdx.x * 128;
    int tid = threadIdx.x;
    int lane = tid & 31, wid = tid >> 5;
    int wm = wid >> 2, wn = wid & 3;
    int group = lane >> 2, tid4 = lane & 3;

    float acc[4][4][4];
    gemm_pipe(sm, sbase, &g_old[(size_t)m0 * KDIM], &g_wc[(size_t)n0 * KDIM], tid, acc);

    #pragma unroll
    for (int mt = 0; mt < 4; mt++) {
        int r0 = m0 + wm * 64 + mt * 16 + group;
        #pragma unroll
        for (int nt = 0; nt < 4; nt++) {
            int c = n0 + wn * 32 + nt * 8 + tid4 * 2;
            *reinterpret_cast<float2*>(&g_dpre[r0 * N_ + c]) =
                make_float2(acc[mt][nt][0], acc[mt][nt][1]);
            *reinterpret_cast<float2*>(&g_dpre[(r0 + 8) * N_ + c]) =
                make_float2(acc[mt][nt][2], acc[mt][nt][3]);
        }
    }
}

// ------------------------------------------------------------------
// K5: Bm GEMM + fused Bu epilogue. BN=128: warp wn owns one n (32 u-cols).
// ------------------------------------------------------------------
__global__ void __launch_bounds__(256, 2) k_gemm_bu(const float* __restrict__ bg,
                                                    const float* __restrict__ u) {
    __shared__ uint32_t sm[3 * STGW];
    uint32_t sbase = (uint32_t)__cvta_generic_to_shared(sm);
    int m0 = blockIdx.y * 128;
    int n0 = blockIdx.x * 128;     // local Bm col
    int tid = threadIdx.x;
    int lane = tid & 31, wid = tid >> 5;
    int wm = wid >> 2, wn = wid & 3;
    int group = lane >> 2, tid4 = lane & 3;

    float acc[4][4][4];
    gemm_pipe(sm, sbase, &g_old[(size_t)m0 * KDIM], &g_wgt[(size_t)n0 * KDIM], tid, acc);

    int nb = blockIdx.x * 4 + wn;
    const float* bgp = &bg[DEL + n0 + wn * 32];

    #pragma unroll
    for (int mt = 0; mt < 4; mt++) {
        int r0 = m0 + wm * 64 + mt * 16 + group;
        int r1 = r0 + 8;
        const float* u0p = &u[((r0 >> 7) * 256 + 127 + (r0 & 127)) * U_];
        const float* u1p = &u[((r1 >> 7) * 256 + 127 + (r1 & 127)) * U_];
        float s0 = 0.0f, s1 = 0.0f;
        #pragma unroll
        for (int nt = 0; nt < 4; nt++) {
            int uu = nt * 8 + tid4 * 2;
            float bg0 = bgp[uu], bg1 = bgp[uu + 1];
            s0 += (acc[mt][nt][0] + bg0) * u0p[uu] + (acc[mt][nt][1] + bg1) * u0p[uu + 1];
            s1 += (acc[mt][nt][2] + bg0) * u1p[uu] + (acc[mt][nt][3] + bg1) * u1p[uu + 1];
        }
        s0 += __shfl_xor_sync(0xffffffffu, s0, 1);
        s0 += __shfl_xor_sync(0xffffffffu, s0, 2);
        s1 += __shfl_xor_sync(0xffffffffu, s1, 1);
        s1 += __shfl_xor_sync(0xffffffffu, s1, 2);
        if (tid4 == 0) {
            g_buraw[r0 * N_ + nb] = s0;
            g_buraw[r1 * N_ + nb] = s1;
        }
    }
}

// ------------------------------------------------------------------
// K6a: delta transform (full chip, in place):
//   g_dpre[idx]  <- dA    = exp(softplus(dpre + bc[n]) * an)
//   g_buraw[idx] <- cbu   = (dA-1)/an * buraw
// Elementwise, race-free. Spreads the MUFU work over 524K threads.
// ------------------------------------------------------------------
__global__ void k_dtrans(const float* __restrict__ A) {
    int idx = blockIdx.x * blockDim.x + threadIdx.x;   // grid 2048 x 256
    int n = idx & 255;
    float a = A[n];
    float an = (a > 0.0f) ? -a : -expm1f(a);
    float acc = g_dpre[idx] + g_bc[n];
    float sp = fmaxf(acc, 0.0f) + log1pf(expf(-fabsf(acc)));
    float dA = expf(sp * an);
    g_dpre[idx] = dA;
    g_buraw[idx] = (dA - 1.0f) / an * g_buraw[idx];
}

// ------------------------------------------------------------------
// K6b: pure scan recurrence: z = z*dA + cbu  (128 blocks x 32 threads).
// ------------------------------------------------------------------
__global__ void __launch_bounds__(32) k_scan(const float* __restrict__ A) {
    int b = blockIdx.x >> 3;
    int n = ((blockIdx.x & 7) << 5) + threadIdx.x;
    float z = g_p[((b << 7) + 127) * N_ + n];
    for (int t0 = 0; t0 < L_; t0 += 8) {
        float da[8], cb[8];
        #pragma unroll
        for (int q = 0; q < 8; q++) {
            int idx = ((b << 7) + t0 + q) * N_ + n;
            da[q] = g_dpre[idx];
            cb[q] = g_buraw[idx];
        }
        #pragma unroll
        for (int q = 0; q < 8; q++) {
            z = z * da[q] + cb[q];
            g_z[((b << 7) + t0 + q) * N_ + n] = z;
        }
    }
}

// ------------------------------------------------------------------
// K7: Cm GEMM + fused y epilogue. Two-phase smem reduction into
// padded ys[128][65], plain stores to per-ntile slice (no atomics).
// ------------------------------------------------------------------
#define YSW 65
#define GSMEM_Y (3 * STGW * 4 + 128 * YSW * 4)

__global__ void __launch_bounds__(256, 2) k_gemm_y(const float* __restrict__ bg) {
    extern __shared__ uint32_t smd[];
    uint32_t* sm = smd;
    float* ys = reinterpret_cast<float*>(smd + 3 * STGW);
    uint32_t sbase = (uint32_t)__cvta_generic_to_shared(sm);
    int m0 = blockIdx.y * 128;
    int nx = blockIdx.x;
    int cb = nx * 128;
    int tid = threadIdx.x;
    int lane = tid & 31, wid = tid >> 5;
    int wm = wid >> 2, wn = wid & 3;
    int group = lane >> 2, tid4 = lane & 3;

    float acc[4][4][4];
    gemm_pipe(sm, sbase, &g_old[(size_t)m0 * KDIM],
              &g_wgt[(size_t)(NBM + cb) * KDIM], tid, acc);

    int nidx = (cb + wn * 32) >> 6;
    const float* bgp = &bg[DEL + NBM + cb + wn * 32];
    int sbase_s = (wn * 32) & 63;

    float yv[4][4][4];
    #pragma unroll
    for (int mt = 0; mt < 4; mt++) {
        int r0 = m0 + wm * 64 + mt * 16 + group;
        float z0 = g_z[r0 * N_ + nidx];
        float z1 = g_z[(r0 + 8) * N_ + nidx];
        #pragma unroll
        for (int nt = 0; nt < 4; nt++) {
            int cc = nt * 8 + tid4 * 2;
            float bg0 = bgp[cc], bg1 = bgp[cc + 1];
            yv[mt][nt][0] = (acc[mt][nt][0] + bg0) * z0;
            yv[mt][nt][1] = (acc[mt][nt][1] + bg1) * z0;
            yv[mt][nt][2] = (acc[mt][nt][2] + bg0) * z1;
            yv[mt][nt][3] = (acc[mt][nt][3] + bg1) * z1;
        }
    }

    __syncthreads();

    if (wn < 2) {
        #pragma unroll
        for (int mt = 0; mt < 4; mt++) {
            int lr = wm * 64 + mt * 16 + group;
            #pragma unroll
            for (int nt = 0; nt < 4; nt++) {
                int s = sbase_s + nt * 8 + tid4 * 2;
                ys[lr * YSW + s]       = yv[mt][nt][0];
                ys[lr * YSW + s + 1]   = yv[mt][nt][1];
                ys[(lr + 8) * YSW + s]     = yv[mt][nt][2];
                ys[(lr + 8) * YSW + s + 1] = yv[mt][nt][3];
            }
        }
    }
    __syncthreads();
    if (wn >= 2) {
        #pragma unroll
        for (int mt = 0; mt < 4; mt++) {
            int lr = wm * 64 + mt * 16 + group;
            #pragma unroll
            for (int nt = 0; nt < 4; nt++) {
                int s = sbase_s + nt * 8 + tid4 * 2;
                ys[lr * YSW + s]       += yv[mt][nt][0];
                ys[lr * YSW + s + 1]   += yv[mt][nt][1];
                ys[(lr + 8) * YSW + s]     += yv[mt][nt][2];
                ys[(lr + 8) * YSW + s + 1] += yv[mt][nt][3];
            }
        }
    }
    __syncthreads();

    float* slice = &g_ys[((size_t)nx * TOK + m0) * S_];
    for (int i = tid; i < 128 * 64; i += 256) {
        int r = i >> 6, s = i & 63;
        slice[r * S_ + s] = ys[r * YSW + s];
    }
}

// ------------------------------------------------------------------
// K8: y finalize: sum 128 slices, write ys output + mse partial.
// ------------------------------------------------------------------
__global__ void k_yfin(const float* __restrict__ x, float* __restrict__ out) {
    __shared__ float red[2];
    int tok = blockIdx.x;
    int b = tok >> 7, t = tok & 127;
    int s = threadIdx.x;   // 0..63
    const float* base = &g_ys[(size_t)tok * S_ + s];
    float yv = 0.0f;
    #pragma unroll 8
    for (int n = 0; n < NYT; n++) yv += base[(size_t)n * TOK * S_];
    out[1 + ((t << 4) + b) * S_ + s] = yv;
    float diff = yv - x[(b * 256 + 128 + t) * S_ + s];
    float v = diff * diff;
    #pragma unroll
    for (int o = 16; o > 0; o >>= 1) v += __shfl_down_sync(0xffffffffu, v, o);
    if ((s & 31) == 0) red[s >> 5] = v;
    __syncthreads();
    if (s == 0) g_part[tok] = red[0] + red[1];
}

// ------------------------------------------------------------------
// K9: loss reduction.
// ------------------------------------------------------------------
__global__ void k_loss(float* __restrict__ out) {
    __shared__ float red[256];
    float v = 0.0f;
    for (int i = threadIdx.x; i < TOK; i += 256) v += g_part[i];
    red[threadIdx.x] = v;
    __syncthreads();
    for (int st = 128; st > 0; st >>= 1) {
        if (threadIdx.x < st) red[threadIdx.x] += red[threadIdx.x + st];
        __syncthreads();
    }
    if (threadIdx.x == 0) out[0] = red[0] / (float)(B_ * S_ * L_);
}

// ------------------------------------------------------------------
// Single linear stream.
// ------------------------------------------------------------------
extern "C" void kernel_launch(void* const* d_in, const int* in_sizes, int n_in,
                              void* d_out, int out_size) {
    const float* x   = (const float*)d_in[0];
    const float* u   = (const float*)d_in[1];
    const float* A   = (const float*)d_in[2];
    const float* W0  = (const float*)d_in[3];
    const float* b0  = (const float*)d_in[4];
    const float* W1  = (const float*)d_in[5];
    const float* b1  = (const float*)d_in[6];
    const float* cw  = (const float*)d_in[7];
    const float* cb  = (const float*)d_in[8];
    const float* Wg  = (const float*)d_in[9];
    const float* bg  = (const float*)d_in[10];
    const float* Wdt = (const float*)d_in[11];
    const float* bdt = (const float*)d_in[12];
    float* out = (float*)d_out;

    cudaFuncSetAttribute(k_gemm_y, cudaFuncAttributeMaxDynamicSharedMemorySize, GSMEM_Y);

    k_proj<<<256, 256>>>(x, W0, b0, W1, b1);
    k_conv<<<TOK, CDIM>>>(u, cw, cb);
    k_wround<<<2048, 256>>>(Wg);
    k_wcomb<<<N_, CDIM>>>(Wg, bg, Wdt, bdt);
    k_gemm_delta<<<dim3(2, 16), 256>>>();
    k_gemm_bu<<<dim3(NBM / 128, 16), 256>>>(bg, u);
    k_dtrans<<<TOK, 256>>>(A);
    k_scan<<<128, 32>>>(A);
    k_gemm_y<<<dim3(NYT, 16), 256, GSMEM_Y>>>(bg);
    k_yfin<<<TOK, S_>>>(x, out);
    k_loss<<<1, 256>>>(out);
}